// round 14
// baseline (speedup 1.0000x reference)
#include <cuda_runtime.h>
#include <cstdint>

// SlidingWindowCmn (16, 60000, 80) fp32, window=600, min=100, center=False,
// norm_vars=True.
// Warp-specialized R6: 128 threads = 4 warps. Threads 0..79 = consumers
// (1 feature each, sliding-window recurrence from a 704-row SMEM ring +8
// mirror). Threads 96..127 = producer warp: issues all distributed 16B
// cp.async fills (lead = 5 groups) and owns cp.async.wait_group, putting
// fill issue + wait latency on the otherwise idle 4th SMSP. One
// __syncthreads per 16-row group publishes completed fills (producer did
// wait_group 4 before arriving). Overwrite safety: issue of group g+5
// overwrites slot-rows 16g-624..-609; concurrent reads are >= 16g-601.

namespace {
constexpr int kB      = 16;
constexpr int kT      = 60000;
constexpr int kF      = 80;
constexpr int kWin    = 600;
constexpr int kMin    = 100;
constexpr int kChunks = 9;
constexpr int kL      = 6672;               // 8*6672 + 6624 = 60000
constexpr int kRL     = 704;                // logical ring rows
constexpr int kRLf    = kRL * kF;           // 56320 floats
constexpr uint32_t kRLb = kRL * 320u;       // 225280 bytes (logical)
constexpr uint32_t kSmemB = (kRL + 8) * 320u;   // 227840 bytes (+8 mirror)
constexpr int kVOf    = (kRL - kWin - 1) * kF;  // 103 rows -> 8240 floats
constexpr float kInvW = 1.0f / 601.0f;
constexpr int kGrid   = kB * kChunks;       // 144
constexpr int kThr    = 128;                // 80 consumers + 16 idle + 32 prod
}

__device__ __forceinline__ uint32_t smem_u32(const void* p) {
    uint32_t a;
    asm("{ .reg .u64 t; cvta.to.shared.u64 t, %1; cvt.u32.u64 %0, t; }"
        : "=r"(a) : "l"(p));
    return a;
}
__device__ __forceinline__ void cpa16(uint32_t s, const float* g) {
    asm volatile("cp.async.cg.shared.global [%0], [%1], 16;" :: "r"(s), "l"(g));
}
__device__ __forceinline__ void cpcommit() {
    asm volatile("cp.async.commit_group;" ::: "memory");
}
__device__ __forceinline__ void cpwait4() {
    asm volatile("cp.async.wait_group 4;" ::: "memory");
}

__global__ void __launch_bounds__(kThr, 1)
cmn_kernel(const float* __restrict__ x, float* __restrict__ out)
{
    extern __shared__ float ring[];
    const int tid  = threadIdx.x;
    const int f    = tid;                        // consumer feature if < 80
    const bool cons = (tid < 80);
    const bool prod = (tid >= 96);
    const int lane  = tid - 96;                  // producer lane 0..31
    const int c = blockIdx.x % kChunks;
    const int b = blockIdx.x / kChunks;

    const float* xb = x + (size_t)b * kT * kF;
    const int start = c * kL;
    const int end   = (c == kChunks - 1) ? kT : start + kL;

    const uint32_t rsb = smem_u32(ring);
    const float* pClamp = x + ((size_t)kB * kT - 16) * kF;  // last full group

    int vnF;                  // consume group float-offset (slot*80)
    uint32_t issB;            // issue group byte-offset (producer)
    const float* pIss;
    if (c == 0) {
        vnF = 0; issB = 0; pIss = xb;
    } else {
        const int t0   = start - 608;            // 7 pad + 601 warmup
        const int slot = t0 % kRL;               // multiple of 16
        vnF = slot * kF; issB = (uint32_t)slot * 320u;
        pIss = xb + (size_t)t0 * kF;
    }

    // producer-only: copy one 16-row group (5120 B), 160 B per lane
    auto issue16 = [&]() {
        const float* q  = (pIss > pClamp) ? pClamp : pIss;
        const float* qt = q + lane * 40;                    // 160 B slice
        const uint32_t a = rsb + issB + (uint32_t)(lane * 160);
        #pragma unroll
        for (int u = 0; u < 10; ++u)
            cpa16(a + 16u * u, qt + 4 * u);
        if (issB == 0) {                 // wrap: mirror rows 0..7 (2560 B)
            const uint32_t m = rsb + kRLb + (uint32_t)(lane * 80);
            const float* qm = q + lane * 20;
            #pragma unroll
            for (int u = 0; u < 5; ++u)
                cpa16(m + 16u * u, qm + 4 * u);
        }
        cpcommit();
        pIss += 16 * kF;
        issB += 5120u; if (issB == kRLb) issB = 0;
    };

    // prologue: producer puts 5 groups in flight, completes the oldest
    if (prod) {
        #pragma unroll 1
        for (int g = 0; g < 5; ++g) issue16();
        cpwait4();
    }

    float s = 0.f, ss = 0.f, mean = 0.f, qss = 0.f;
    float* po = out + (size_t)b * kT * kF + f;
    int nSteady;

    if (c == 0) {
        // groups 0..5: rows 0..95 accumulate
        #pragma unroll 1
        for (int g = 0; g < 6; ++g) {
            __syncthreads();
            if (cons) {
                const float* rv = ring + vnF + f;
                #pragma unroll
                for (int u = 0; u < 16; ++u) {
                    float v = rv[u * kF]; s += v; ss = __fmaf_rn(v, v, ss);
                }
            }
            vnF += 16 * kF;
            if (prod) { issue16(); cpwait4(); }
        }
        // group 6: rows 96..111
        {
            __syncthreads();
            if (cons) {
                const float* rv = ring + vnF + f;
                #pragma unroll
                for (int u = 0; u < 4; ++u) {          // rows 96..99
                    float v = rv[u * kF]; s += v; ss = __fmaf_rn(v, v, ss);
                }
                const float inv = 1.0f / (float)kMin;  // burst rows 0..99
                const float m0  = s * inv;
                const float vr0 = __fmaf_rn(-m0, m0, ss * inv);
                const float rs0 = rsqrtf(vr0);
                #pragma unroll 4
                for (int t = 0; t < kMin; ++t) {
                    float v = ring[t * kF + f];
                    __stcs(po + t * kF, (v - m0) * rs0);
                }
                float n = 100.0f;
                #pragma unroll
                for (int u = 4; u < 16; ++u) {         // rows 100..111 growing
                    float v = rv[u * kF]; s += v; ss = __fmaf_rn(v, v, ss);
                    n += 1.0f;
                    float inv2 = __fdividef(1.0f, n);
                    float m    = s * inv2;
                    float var  = __fmaf_rn(-m, m, ss * inv2);
                    __stcs(po + (96 + u) * kF, (v - m) * rsqrtf(var));
                }
            }
            vnF += 16 * kF;
            if (prod) { issue16(); cpwait4(); }
        }
        // groups 7..36: rows 112..591 growing
        po += 112 * kF;
        float n = 112.0f;
        #pragma unroll 1
        for (int g = 7; g < 37; ++g) {
            __syncthreads();
            if (cons) {
                const float* rv = ring + vnF + f;
                #pragma unroll
                for (int u = 0; u < 16; ++u) {
                    float v = rv[u * kF]; s += v; ss = __fmaf_rn(v, v, ss);
                    n += 1.0f;
                    float inv = __fdividef(1.0f, n);
                    float m   = s * inv;
                    float var = __fmaf_rn(-m, m, ss * inv);
                    __stcs(po + u * kF, (v - m) * rsqrtf(var));
                }
            }
            vnF += 16 * kF; po += 16 * kF;
            if (prod) { issue16(); cpwait4(); }
        }
        // group 37: rows 592..607 (transition at t=600)
        {
            __syncthreads();
            if (cons) {
                const float* rv = ring + vnF + f;
                #pragma unroll
                for (int u = 0; u < 8; ++u) {          // rows 592..599 growing
                    float v = rv[u * kF]; s += v; ss = __fmaf_rn(v, v, ss);
                    n += 1.0f;
                    float inv = __fdividef(1.0f, n);
                    float m   = s * inv;
                    float var = __fmaf_rn(-m, m, ss * inv);
                    __stcs(po + u * kF, (v - m) * rsqrtf(var));
                }
                mean = s * kInvW; qss = ss * kInvW;
                #pragma unroll
                for (int u = 8; u < 16; ++u) {         // rows 600..607 steady-1
                    float vn = rv[u * kF];
                    float vo = (u == 8) ? 0.0f : ring[(u - 9) * kF + f];
                    float t1 = (vn - vo) * kInvW;
                    mean += t1;
                    qss   = __fmaf_rn(t1, vn + vo, qss);
                    float var = __fmaf_rn(-mean, mean, qss);
                    __stcs(po + u * kF, (vn - mean) * rsqrtf(var));
                }
            }
            vnF += 16 * kF;                            // vnF = 608*kF
            if (prod) { issue16(); cpwait4(); }
        }
        nSteady = (kL - 608) / 16;                     // 379
    } else {
        // warmup group 0: rows t0+7 .. t0+15 (start-601 .. start-593)
        {
            __syncthreads();
            if (cons) {
                const float* rv = ring + vnF + f;
                #pragma unroll
                for (int u = 7; u < 16; ++u) {
                    float v = rv[u * kF]; s += v; ss = __fmaf_rn(v, v, ss);
                }
            }
            vnF += 16 * kF; if (vnF == kRLf) vnF = 0;
            if (prod) { issue16(); cpwait4(); }
        }
        // warmup groups 1..37: 592 rows
        #pragma unroll 1
        for (int g = 1; g < 38; ++g) {
            __syncthreads();
            if (cons) {
                const float* rv = ring + vnF + f;
                #pragma unroll
                for (int u = 0; u < 16; ++u) {
                    float v = rv[u * kF]; s += v; ss = __fmaf_rn(v, v, ss);
                }
            }
            vnF += 16 * kF; if (vnF == kRLf) vnF = 0;
            if (prod) { issue16(); cpwait4(); }
        }
        mean = s * kInvW; qss = ss * kInvW;
        nSteady = (end - start) / 16;                  // 417 or 414
    }

    // ---- steady sliding loop ----
    const int g0row = (c == 0) ? 608 : start;
    float* po2 = out + (size_t)b * kT * kF + (size_t)g0row * kF + f;
    #pragma unroll 1
    for (int g = 0; g < nSteady; ++g) {
        __syncthreads();                  // group g complete; slots safe
        if (cons) {
            const float* rvn = ring + vnF + f;
            int voF = vnF + kVOf;                     // slot (t-601)
            if (voF >= kRLf) voF -= kRLf;             // one check / 16 rows
            const float* rvo = ring + voF + f;        // mirror covers straddle
            #pragma unroll
            for (int u = 0; u < 16; ++u) {
                float vn = rvn[u * kF];
                float vo = rvo[u * kF];
                float t1 = (vn - vo) * kInvW;
                mean += t1;
                qss   = __fmaf_rn(t1, vn + vo, qss);
                float var = __fmaf_rn(-mean, mean, qss);
                __stcs(po2 + u * kF, (vn - mean) * rsqrtf(var));
            }
        }
        vnF += 16 * kF; if (vnF == kRLf) vnF = 0;
        po2 += 16 * kF;
        if (prod) { issue16(); cpwait4(); }
    }
}

extern "C" void kernel_launch(void* const* d_in, const int* in_sizes, int n_in,
                              void* d_out, int out_size)
{
    const float* x = (const float*)d_in[0];
    float* o = (float*)d_out;
    (void)in_sizes; (void)n_in; (void)out_size;

    cudaFuncSetAttribute(cmn_kernel,
                         cudaFuncAttributeMaxDynamicSharedMemorySize, (int)kSmemB);
    cmn_kernel<<<kGrid, kThr, kSmemB>>>(x, o);
}

// round 15
// speedup vs baseline: 1.1536x; 1.1536x over previous
#include <cuda_runtime.h>
#include <cstdint>

// SlidingWindowCmn (16, 60000, 80) fp32, window=600, min=100, center=False,
// norm_vars=True.
// CONVERGED KERNEL (R6, 127.2us): distributed 16B cp.async -> 704-row SMEM
// ring (+8 mirror) -> per-thread sliding window (1 thread/feature).
// 16-row groups, wait_group 4 + __syncthreads per group, lead = 5 groups
// (cross-thread overwrite safety: 16*5 + 15 <= (704-601) - 1).
// Per-SM LSU dispatch (~30 cyc/row: 2.5 STG.32 + 5 LDS + 0.625 LDGSTS
// warp-ops) is the measured wall; DRAM traffic is at the 597 MB floor.

namespace {
constexpr int kB      = 16;
constexpr int kT      = 60000;
constexpr int kF      = 80;
constexpr int kWin    = 600;
constexpr int kMin    = 100;
constexpr int kChunks = 9;
constexpr int kL      = 6672;               // 8*6672 + 6624 = 60000
constexpr int kRL     = 704;                // logical ring rows
constexpr int kRLf    = kRL * kF;           // 56320 floats
constexpr uint32_t kRLb = kRL * 320u;       // 225280 bytes (logical)
constexpr uint32_t kSmemB = (kRL + 8) * 320u;   // 227840 bytes (+8 mirror)
constexpr int kVOf    = (kRL - kWin - 1) * kF;  // 103 rows -> 8240 floats
constexpr float kInvW = 1.0f / 601.0f;
constexpr int kGrid   = kB * kChunks;       // 144
}

__device__ __forceinline__ uint32_t smem_u32(const void* p) {
    uint32_t a;
    asm("{ .reg .u64 t; cvta.to.shared.u64 t, %1; cvt.u32.u64 %0, t; }"
        : "=r"(a) : "l"(p));
    return a;
}
__device__ __forceinline__ void cpa16(uint32_t s, const float* g) {
    asm volatile("cp.async.cg.shared.global [%0], [%1], 16;" :: "r"(s), "l"(g));
}
__device__ __forceinline__ void cpcommit() {
    asm volatile("cp.async.commit_group;" ::: "memory");
}
__device__ __forceinline__ void cpwait4() {
    asm volatile("cp.async.wait_group 4;" ::: "memory");
}

__global__ void __launch_bounds__(kF, 1)
cmn_kernel(const float* __restrict__ x, float* __restrict__ out)
{
    extern __shared__ float ring[];
    const int f = threadIdx.x;                    // feature 0..79
    const int c = blockIdx.x % kChunks;
    const int b = blockIdx.x / kChunks;

    const float* xb = x + (size_t)b * kT * kF;
    const int start = c * kL;
    const int end   = (c == kChunks - 1) ? kT : start + kL;

    const uint32_t rsb = smem_u32(ring);
    const float* pClamp = x + ((size_t)kB * kT - 16) * kF;  // last full group

    int vnF;                  // consume group float-offset (slot*80)
    uint32_t issB;            // issue group byte-offset
    const float* pIss;
    if (c == 0) {
        vnF = 0; issB = 0; pIss = xb;
    } else {
        const int t0   = start - 608;             // 16-aligned; 7 pad + 601 warmup
        const int slot = t0 % kRL;                // multiple of 16
        vnF = slot * kF; issB = (uint32_t)slot * 320u;
        pIss = xb + (size_t)t0 * kF;
    }

    auto issue16 = [&]() {
        const float* q  = (pIss > pClamp) ? pClamp : pIss;
        const float* qt = q + f * 4;                         // 16B per thread
        const uint32_t a = rsb + issB + (uint32_t)(f << 4);
        cpa16(a,         qt);
        cpa16(a + 1280u, qt + 320);
        cpa16(a + 2560u, qt + 640);
        cpa16(a + 3840u, qt + 960);
        if (issB == 0) {                          // wrap group: mirror rows 0..7
            const uint32_t m = rsb + kRLb + (uint32_t)(f << 4);
            cpa16(m,         qt);
            cpa16(m + 1280u, qt + 320);
        }
        cpcommit();
        pIss += 16 * kF;
        issB += 5120u; if (issB == kRLb) issB = 0;
    };

    // prologue: 5 groups (80 rows) in flight
    #pragma unroll 1
    for (int g = 0; g < 5; ++g) issue16();

    float s = 0.f, ss = 0.f, mean = 0.f, qss = 0.f;
    float* po = out + (size_t)b * kT * kF + f;
    int nSteady;

    if (c == 0) {
        // groups 0..5: rows 0..95 accumulate
        #pragma unroll 1
        for (int g = 0; g < 6; ++g) {
            cpwait4(); __syncthreads();
            const float* rv = ring + vnF + f;
            #pragma unroll
            for (int u = 0; u < 16; ++u) {
                float v = rv[u * kF]; s += v; ss = __fmaf_rn(v, v, ss);
            }
            vnF += 16 * kF; issue16();
        }
        // group 6: rows 96..111
        {
            cpwait4(); __syncthreads();
            const float* rv = ring + vnF + f;
            #pragma unroll
            for (int u = 0; u < 4; ++u) {          // rows 96..99
                float v = rv[u * kF]; s += v; ss = __fmaf_rn(v, v, ss);
            }
            const float inv = 1.0f / (float)kMin;  // burst rows 0..99
            const float m0  = s * inv;
            const float vr0 = __fmaf_rn(-m0, m0, ss * inv);
            const float rs0 = rsqrtf(vr0);
            #pragma unroll 4
            for (int t = 0; t < kMin; ++t) {
                float v = ring[t * kF + f];
                __stcs(po + t * kF, (v - m0) * rs0);
            }
            float n = 100.0f;
            #pragma unroll
            for (int u = 4; u < 16; ++u) {         // rows 100..111 growing
                float v = rv[u * kF]; s += v; ss = __fmaf_rn(v, v, ss);
                n += 1.0f;
                float inv2 = __fdividef(1.0f, n);
                float m    = s * inv2;
                float var  = __fmaf_rn(-m, m, ss * inv2);
                __stcs(po + (96 + u) * kF, (v - m) * rsqrtf(var));
            }
            vnF += 16 * kF; issue16();
        }
        // groups 7..36: rows 112..591 growing
        po += 112 * kF;
        float n = 112.0f;
        #pragma unroll 1
        for (int g = 7; g < 37; ++g) {
            cpwait4(); __syncthreads();
            const float* rv = ring + vnF + f;
            #pragma unroll
            for (int u = 0; u < 16; ++u) {
                float v = rv[u * kF]; s += v; ss = __fmaf_rn(v, v, ss);
                n += 1.0f;
                float inv = __fdividef(1.0f, n);
                float m   = s * inv;
                float var = __fmaf_rn(-m, m, ss * inv);
                __stcs(po + u * kF, (v - m) * rsqrtf(var));
            }
            vnF += 16 * kF; po += 16 * kF; issue16();
        }
        // group 37: rows 592..607 (transition at t=600)
        {
            cpwait4(); __syncthreads();
            const float* rv = ring + vnF + f;
            #pragma unroll
            for (int u = 0; u < 8; ++u) {          // rows 592..599 growing
                float v = rv[u * kF]; s += v; ss = __fmaf_rn(v, v, ss);
                n += 1.0f;
                float inv = __fdividef(1.0f, n);
                float m   = s * inv;
                float var = __fmaf_rn(-m, m, ss * inv);
                __stcs(po + u * kF, (v - m) * rsqrtf(var));
            }
            mean = s * kInvW; qss = ss * kInvW;
            #pragma unroll
            for (int u = 8; u < 16; ++u) {         // rows 600..607 steady-1
                float vn = rv[u * kF];
                float vo = (u == 8) ? 0.0f : ring[(u - 9) * kF + f];
                float t1 = (vn - vo) * kInvW;
                mean += t1;
                qss   = __fmaf_rn(t1, vn + vo, qss);
                float var = __fmaf_rn(-mean, mean, qss);
                __stcs(po + u * kF, (vn - mean) * rsqrtf(var));
            }
            vnF += 16 * kF; issue16();             // vnF = 608*kF
        }
        nSteady = (kL - 608) / 16;                 // 379
    } else {
        // warmup group 0: rows t0+7 .. t0+15 (start-601 .. start-593)
        {
            cpwait4(); __syncthreads();
            const float* rv = ring + vnF + f;
            #pragma unroll
            for (int u = 7; u < 16; ++u) {
                float v = rv[u * kF]; s += v; ss = __fmaf_rn(v, v, ss);
            }
            vnF += 16 * kF; if (vnF == kRLf) vnF = 0;
            issue16();
        }
        // warmup groups 1..37: 592 rows
        #pragma unroll 1
        for (int g = 1; g < 38; ++g) {
            cpwait4(); __syncthreads();
            const float* rv = ring + vnF + f;
            #pragma unroll
            for (int u = 0; u < 16; ++u) {
                float v = rv[u * kF]; s += v; ss = __fmaf_rn(v, v, ss);
            }
            vnF += 16 * kF; if (vnF == kRLf) vnF = 0;
            issue16();
        }
        mean = s * kInvW; qss = ss * kInvW;
        nSteady = (end - start) / 16;              // 417 or 414
    }

    // ---- steady sliding loop ----
    const int g0row = (c == 0) ? 608 : start;
    float* po2 = out + (size_t)b * kT * kF + (size_t)g0row * kF + f;
    #pragma unroll 1
    for (int g = 0; g < nSteady; ++g) {
        cpwait4(); __syncthreads();
        const float* rvn = ring + vnF + f;
        int voF = vnF + kVOf;                      // slot (t-601), group-aligned
        if (voF >= kRLf) voF -= kRLf;              // one wrap check / 16 rows
        const float* rvo = ring + voF + f;         // mirror covers straddle
        #pragma unroll
        for (int u = 0; u < 16; ++u) {
            float vn = rvn[u * kF];
            float vo = rvo[u * kF];
            float t1 = (vn - vo) * kInvW;
            mean += t1;
            qss   = __fmaf_rn(t1, vn + vo, qss);
            float var = __fmaf_rn(-mean, mean, qss);
            __stcs(po2 + u * kF, (vn - mean) * rsqrtf(var));
        }
        vnF += 16 * kF; if (vnF == kRLf) vnF = 0;
        po2 += 16 * kF;
        issue16();
    }
}

extern "C" void kernel_launch(void* const* d_in, const int* in_sizes, int n_in,
                              void* d_out, int out_size)
{
    const float* x = (const float*)d_in[0];
    float* o = (float*)d_out;
    (void)in_sizes; (void)n_in; (void)out_size;

    cudaFuncSetAttribute(cmn_kernel,
                         cudaFuncAttributeMaxDynamicSharedMemorySize, (int)kSmemB);
    cmn_kernel<<<kGrid, kF, kSmemB>>>(x, o);
}